// round 8
// baseline (speedup 1.0000x reference)
#include <cuda_runtime.h>
#include <stdint.h>

// ---------------- problem constants ----------------
#define NVAR 4
#define BATCH 32
#define TSTEPS 256
#define KLANES 1024          // NOUT * NFEAT

struct Keys { unsigned v[20]; };

static __device__ float g_w2[NVAR * 1057 * 32];            // reordered: [0..31]=a1 ch, [32..1055]=y2 k, [1056]=bias
static __device__ float g_a1s[NVAR * BATCH * 32 * TSTEPS]; // [n][b][c][t]
static __device__ float g_beta1[NVAR * TSTEPS * KLANES];   // [n][t][k]
static __device__ float g_beta2[NVAR * TSTEPS * KLANES];

// ---------------- threefry2x32-20 (JAX-compatible), device ----------------
__device__ __forceinline__ void tf2x32(unsigned k0, unsigned k1,
                                       unsigned x0, unsigned x1,
                                       unsigned& o0, unsigned& o1) {
    unsigned ks2 = k0 ^ k1 ^ 0x1BD11BDAu;
    x0 += k0; x1 += k1;
#define TFR(r) { x0 += x1; x1 = (x1 << (r)) | (x1 >> (32 - (r))); x1 ^= x0; }
    TFR(13) TFR(15) TFR(26) TFR(6)
    x0 += k1; x1 += ks2 + 1u;
    TFR(17) TFR(29) TFR(16) TFR(24)
    x0 += ks2; x1 += k0 + 2u;
    TFR(13) TFR(15) TFR(26) TFR(6)
    x0 += k0; x1 += k1 + 3u;
    TFR(17) TFR(29) TFR(16) TFR(24)
    x0 += k1; x1 += ks2 + 4u;
    TFR(13) TFR(15) TFR(26) TFR(6)
    x0 += ks2; x1 += k0 + 5u;
#undef TFR
    o0 = x0; o1 = x1;
}

__device__ __forceinline__ float tf_uniform(unsigned k0, unsigned k1, unsigned ctr) {
    unsigned o0, o1;
    tf2x32(k0, k1, 0u, ctr, o0, o1);
    unsigned bits = o0 ^ o1;
    return __uint_as_float((bits >> 9) | 0x3f800000u) - 1.0f;
}

__device__ __forceinline__ float sigmoidf_(float x) {
    return 1.0f / (1.0f + expf(-x));
}

__device__ __forceinline__ float theta_eff(float t) {
    t = fminf(fmaxf(t, -10.0f), 10.0f);
    if (fabsf(t) < 0.01f) t = 0.0f;
    return t;
}

// ---------------- cp.async helpers ----------------
__device__ __forceinline__ void cp16(uint32_t smem_addr, const void* gptr) {
    asm volatile("cp.async.ca.shared.global [%0], [%1], 16;\n"
                 :: "r"(smem_addr), "l"(gptr));
}
__device__ __forceinline__ void cp_commit() {
    asm volatile("cp.async.commit_group;\n" ::: "memory");
}
__device__ __forceinline__ void cp_wait0() {
    asm volatile("cp.async.wait_group 0;\n" ::: "memory");
}
__device__ __forceinline__ void cp_wait1() {
    asm volatile("cp.async.wait_group 1;\n" ::: "memory");
}

// ================= megakernel A: beta | pmac1(+w1) | prep_w2 =================
__global__ void __launch_bounds__(256) k_A(Keys kk,
                                           const float* __restrict__ x,
                                           const float* __restrict__ theta1,
                                           const float* __restrict__ theta2,
                                           const float* __restrict__ Rlf,
                                           const float* __restrict__ Clf) {
    int blk = blockIdx.x;
    int tid = threadIdx.x;

    if (blk < 8192) {
        // -------- beta tables, layout [n][t][k] --------
        unsigned gid = (unsigned)blk * 256u + (unsigned)tid;   // 0 .. 2M-1
        int bank = gid >> 20;
        unsigned rest = gid & 0xFFFFFu;
        int k = rest & 1023;
        int n = (rest >> 10) & 3;
        int t = rest >> 12;
        int off = 4 + bank * 8;
        unsigned ctr = (unsigned)(((t * 1024) + k) * 4 + n);   // iota over (T,K,N,1)
        float nR = (tf_uniform(kk.v[off + 0], kk.v[off + 1], ctr) * 2.0f - 1.0f) * 0.05f + 1.0f;
        float nC = (tf_uniform(kk.v[off + 2], kk.v[off + 3], ctr) * 2.0f - 1.0f) * 0.05f + 1.0f;
        float mu = tf_uniform(kk.v[off + 4], kk.v[off + 5], ctr) * 0.2f + 1.0f;
        float R_ = Rlf[k * 2 + bank];
        float C_ = Clf[k * 2 + bank];
        float Rt = sigmoidf_(R_) * (1e7f - 1e5f) + 1e5f;
        float Ct = sigmoidf_(C_) * (1e-4f - 1e-7f) + 1e-7f;
        float RC = mu * (Rt * nR) * (Ct * nC);
        float beta = RC / (RC + 0.1f);
        float* dst = bank ? g_beta2 : g_beta1;
        dst[(n * 256 + t) * 1024 + k] = beta;

    } else if (blk < 8320) {
        // -------- pmac1: block=(n,b), thread=t --------
        __shared__ float w[33 * 32];
        int blk2 = blk - 8192;
        int n = blk2 >> 5, b = blk2 & 31;
        if (tid < 32) {
            int o = tid;
            float den = 0.0f;
            for (int m = 0; m < 34; m++) {
                float th = theta_eff(theta1[m * 32 + o]);
                float u = tf_uniform(kk.v[0], kk.v[1], (unsigned)((n * 34 + m) * 32 + o));
                float noise = (u * 2.0f - 1.0f) * 0.05f + 1.0f;
                float thn = th * noise;
                den += fabsf(thn);
                if (m < 33) w[m * 32 + o] = thn;
            }
            den += 1e-10f;
            for (int m = 0; m < 33; m++) w[m * 32 + o] = w[m * 32 + o] / den;
        }
        __syncthreads();
        int t = tid;
        float z[32];
#pragma unroll
        for (int o = 0; o < 32; o++) z[o] = w[32 * 32 + o];
        const float* xp = x + ((n * 32 + b) * 32) * 256 + t;
#pragma unroll 4
        for (int m = 0; m < 32; m++) {
            float xv = xp[m * 256];
#pragma unroll
            for (int o = 0; o < 32; o++) z[o] = fmaf(xv, w[m * 32 + o], z[o]);
        }
#pragma unroll
        for (int o = 0; o < 32; o++) {
            float a = 0.05f + 0.5f * tanhf((z[o] - 0.3f) * 3.0f);
            g_a1s[(((n * 32 + b) * 32) + o) * 256 + t] = a;
        }

    } else {
        // -------- prep_w2 (reordered) --------
        __shared__ float sh[256];
        int blk3 = blk - 8320;
        int n = blk3 >> 5, o = blk3 & 31;
        unsigned nk0 = kk.v[2], nk1 = kk.v[3];
        float part = 0.0f;
        for (int m = tid; m < 1058; m += 256) {
            float th = theta_eff(theta2[m * 32 + o]);
            float u = tf_uniform(nk0, nk1, (unsigned)((n * 1058 + m) * 32 + o));
            float noise = (u * 2.0f - 1.0f) * 0.05f + 1.0f;
            part += fabsf(th * noise);
        }
        sh[tid] = part;
        __syncthreads();
        for (int s = 128; s > 0; s >>= 1) {
            if (tid < s) sh[tid] += sh[tid + s];
            __syncthreads();
        }
        float den = sh[0] + 1e-10f;
        for (int m = tid; m < 1057; m += 256) {
            float th = theta_eff(theta2[m * 32 + o]);
            float u = tf_uniform(nk0, nk1, (unsigned)((n * 1058 + m) * 32 + o));
            float noise = (u * 2.0f - 1.0f) * 0.05f + 1.0f;
            float wv = (th * noise) / den;
            int mm;
            if (m == 1056) mm = 1056;
            else {
                int c = m / 33, r = m % 33;
                mm = (r == 0) ? c : (32 + c * 32 + (r - 1));
            }
            g_w2[(n * 1057 + mm) * 32 + o] = wv;
        }
    }
}

// ================= FUSED scan + pmac2 GEMM (pipelined, 2 barriers/chunk) =================
// block = (n,b): 128 blocks x 1024 threads. Chunk = 8 timesteps.
// smem (floats): WS[1088] | Y[1024][8] | RED[8*32*32 swizzled] | A1[2][8][32] | BB[2][2][8][1024]
#define SM_WS  0
#define SM_Y   1088
#define SM_RED 9280
#define SM_A1  17472
#define SM_BB  17984
#define SM_TOT 50752          // floats -> 203008 bytes

__global__ void __launch_bounds__(1024, 1) k_fused(Keys kk, float* __restrict__ out) {
    extern __shared__ float sm[];
    float* ws_s  = sm + SM_WS;    // [0..1023] a1-ch weights, [1024..1055] bias
    float* y_s   = sm + SM_Y;     // [k][8]
    float* red_s = sm + SM_RED;   // [(tt*32+ks)*32 + (o^j-swizzle)]
    float* a1_s  = sm + SM_A1;    // [parity][tt][c]
    float* bb_s  = sm + SM_BB;    // [buf][bank][tt][k]

    int n = blockIdx.x >> 5, b = blockIdx.x & 31;
    int tid  = threadIdx.x;
    int ks   = tid >> 5;          // warp id = k-slice
    int lane = tid & 31;          // = o in GEMM phase

    const float* wg = g_w2 + n * (1057 * 32);

    // ---- small weight block to smem ----
    ws_s[tid & 1023] = wg[tid & 1023];
    if (tid < 32) ws_s[1024 + tid] = wg[1056 * 32 + tid];

    // ---- register-resident W slice: W[32+ks*32+j][lane] ----
    float wreg[32];
    {
        const float* wp = wg + (32 + ks * 32) * 32 + lane;
#pragma unroll
        for (int j = 0; j < 32; j++) wreg[j] = wp[j * 32];
    }

    // ---- scan lane setup: thread = k = tid ----
    int k = tid;
    int c = ks;
    unsigned sctr = (unsigned)((k * 4 + n) * 32 + b);
    float s1 = tf_uniform(kk.v[10], kk.v[11], sctr);
    float s2 = tf_uniform(kk.v[18], kk.v[19], sctr);
    const float* xbase = g_a1s + (((n * 32 + b) * 32) + c) * 256;  // [n][b][c][t]
    const float* bet1  = g_beta1 + n * 256 * 1024;
    const float* bet2  = g_beta2 + n * 256 * 1024;

    uint32_t bb_base = (uint32_t)__cvta_generic_to_shared(bb_s);

    // ---- prefetch beta chunks 0 and 1 (separate groups) ----
    {
        int q = tid;
        uint32_t d0 = bb_base;
        cp16(d0 + q * 16,              bet1 + q * 4);
        cp16(d0 + 4096 * 4 + q * 16,   bet1 + 4096 + q * 4);
        cp16(d0 + 8192 * 4 + q * 16,   bet2 + q * 4);
        cp16(d0 + 12288 * 4 + q * 16,  bet2 + 4096 + q * 4);
        cp_commit();
        uint32_t d1 = bb_base + 16384 * 4;
        cp16(d1 + q * 16,              bet1 + 8192 + q * 4);
        cp16(d1 + 4096 * 4 + q * 16,   bet1 + 8192 + 4096 + q * 4);
        cp16(d1 + 8192 * 4 + q * 16,   bet2 + 8192 + q * 4);
        cp16(d1 + 12288 * 4 + q * 16,  bet2 + 8192 + 4096 + q * 4);
        cp_commit();
    }

    // ---- reduce map (tid < 256) ----
    int rt = tid >> 5, ro = tid & 31;

    float yv[8];

    // ---- prologue: scan chunk 0, store to y_s ----
    cp_wait1();            // chunk-0 group done
    __syncthreads();
    {
        const float* bbp = bb_s;   // buf 0
#pragma unroll
        for (int tt = 0; tt < 8; tt++) {
            float b1 = bbp[tt * 1024 + k];
            float b2 = bbp[8192 + tt * 1024 + k];
            float xv = xbase[tt];
            if (lane == 0) a1_s[tt * 32 + c] = xv;    // parity 0
            float y1 = s1;
            s1 = b1 * s1 + (1.0f - b1) * xv;
            yv[tt] = s2;
            s2 = b2 * s2 + (1.0f - b2) * y1;
        }
        *(float4*)(y_s + k * 8)     = make_float4(yv[0], yv[1], yv[2], yv[3]);
        *(float4*)(y_s + k * 8 + 4) = make_float4(yv[4], yv[5], yv[6], yv[7]);
    }
    __syncthreads();

    for (int ch = 0; ch < 32; ch++) {
        int par  = ch & 1;

        // ---- prefetch beta chunk ch+2 into bb[ch&1] ----
        if (ch <= 29) {
            int tn = (ch + 2) * 8;
            int q = tid;
            uint32_t dst = bb_base + (unsigned)(ch & 1) * 16384 * 4;
            cp16(dst + q * 16,             bet1 + tn * 1024 + q * 4);
            cp16(dst + 4096 * 4 + q * 16,  bet1 + tn * 1024 + 4096 + q * 4);
            cp16(dst + 8192 * 4 + q * 16,  bet2 + tn * 1024 + q * 4);
            cp16(dst + 12288 * 4 + q * 16, bet2 + tn * 1024 + 4096 + q * 4);
            cp_commit();
            cp_wait1();        // chunk ch+1 ready (1 outstanding = ch+2)
        } else {
            cp_wait0();        // tail: everything done
        }

        // ===== scan chunk ch+1 -> yv regs (independent of GEMM below) =====
        if (ch < 31) {
            const float* bbp = bb_s + ((ch + 1) & 1) * 16384;
            int tbase = (ch + 1) * 8;
#pragma unroll
            for (int tt = 0; tt < 8; tt++) {
                float b1 = bbp[tt * 1024 + k];
                float b2 = bbp[8192 + tt * 1024 + k];
                float xv = xbase[tbase + tt];
                if (lane == 0) a1_s[(par ^ 1) * 256 + tt * 32 + c] = xv;
                float y1 = s1;
                s1 = b1 * s1 + (1.0f - b1) * xv;
                yv[tt] = s2;
                s2 = b2 * s2 + (1.0f - b2) * y1;
            }
        }

        // ===== GEMM chunk ch from y_s (packed f32x2) =====
        {
            unsigned long long a01 = 0ull, a23 = 0ull, a45 = 0ull, a67 = 0ull;
            const float* yrow = y_s + ks * 256;   // 32 rows of 8
#pragma unroll
            for (int j = 0; j < 32; j++) {
                ulonglong2 u0 = *(const ulonglong2*)(yrow + j * 8);
                ulonglong2 u1 = *(const ulonglong2*)(yrow + j * 8 + 4);
                unsigned long long wp2;
                asm("mov.b64 %0, {%1, %1};" : "=l"(wp2) : "f"(wreg[j]));
                asm("fma.rn.f32x2 %0, %1, %2, %0;" : "+l"(a01) : "l"(wp2), "l"(u0.x));
                asm("fma.rn.f32x2 %0, %1, %2, %0;" : "+l"(a23) : "l"(wp2), "l"(u0.y));
                asm("fma.rn.f32x2 %0, %1, %2, %0;" : "+l"(a45) : "l"(wp2), "l"(u1.x));
                asm("fma.rn.f32x2 %0, %1, %2, %0;" : "+l"(a67) : "l"(wp2), "l"(u1.y));
            }
            int col = lane ^ ks;   // XOR swizzle: conflict-free store & reduce
            float v0, v1;
            asm("mov.b64 {%0, %1}, %2;" : "=f"(v0), "=f"(v1) : "l"(a01));
            red_s[(0 * 32 + ks) * 32 + col] = v0;
            red_s[(1 * 32 + ks) * 32 + col] = v1;
            asm("mov.b64 {%0, %1}, %2;" : "=f"(v0), "=f"(v1) : "l"(a23));
            red_s[(2 * 32 + ks) * 32 + col] = v0;
            red_s[(3 * 32 + ks) * 32 + col] = v1;
            asm("mov.b64 {%0, %1}, %2;" : "=f"(v0), "=f"(v1) : "l"(a45));
            red_s[(4 * 32 + ks) * 32 + col] = v0;
            red_s[(5 * 32 + ks) * 32 + col] = v1;
            asm("mov.b64 {%0, %1}, %2;" : "=f"(v0), "=f"(v1) : "l"(a67));
            red_s[(6 * 32 + ks) * 32 + col] = v0;
            red_s[(7 * 32 + ks) * 32 + col] = v1;
        }
        __syncthreads();

        // ===== store yv -> y_s (for next chunk's GEMM) =====
        if (ch < 31) {
            *(float4*)(y_s + k * 8)     = make_float4(yv[0], yv[1], yv[2], yv[3]);
            *(float4*)(y_s + k * 8 + 4) = make_float4(yv[4], yv[5], yv[6], yv[7]);
        }

        // ===== reduce chunk ch + a1 term + bias + act + store =====
        if (tid < 256) {
            float z0 = ws_s[1024 + ro];          // bias
            float z1 = 0.f, z2 = 0.f, z3 = 0.f;
            const float* rrow = red_s + rt * 32 * 32;
            const float* arow = a1_s + par * 256 + rt * 32;
#pragma unroll
            for (int j = 0; j < 32; j += 4) {
                z0 += rrow[(j + 0) * 32 + (ro ^ (j + 0))];
                z1 += rrow[(j + 1) * 32 + (ro ^ (j + 1))];
                z2 += rrow[(j + 2) * 32 + (ro ^ (j + 2))];
                z3 += rrow[(j + 3) * 32 + (ro ^ (j + 3))];
            }
#pragma unroll
            for (int cc = 0; cc < 32; cc += 4) {
                z0 = fmaf(ws_s[(cc + 0) * 32 + ro], arow[cc + 0], z0);
                z1 = fmaf(ws_s[(cc + 1) * 32 + ro], arow[cc + 1], z1);
                z2 = fmaf(ws_s[(cc + 2) * 32 + ro], arow[cc + 2], z2);
                z3 = fmaf(ws_s[(cc + 3) * 32 + ro], arow[cc + 3], z3);
            }
            float z = (z0 + z1) + (z2 + z3);
            float a = 0.05f + 0.5f * tanhf((z - 0.3f) * 3.0f);
            out[((n * 32 + b) * 32 + ro) * 256 + ch * 8 + rt] = a;
        }
        __syncthreads();
    }
}

// ---------------- host-side threefry for key derivation ----------------
static void h_tf2x32(unsigned k0, unsigned k1, unsigned x0, unsigned x1,
                     unsigned& o0, unsigned& o1) {
    unsigned ks2 = k0 ^ k1 ^ 0x1BD11BDAu;
    x0 += k0; x1 += k1;
#define HTFR(r) { x0 += x1; x1 = (x1 << (r)) | (x1 >> (32 - (r))); x1 ^= x0; }
    HTFR(13) HTFR(15) HTFR(26) HTFR(6)
    x0 += k1; x1 += ks2 + 1u;
    HTFR(17) HTFR(29) HTFR(16) HTFR(24)
    x0 += ks2; x1 += k0 + 2u;
    HTFR(13) HTFR(15) HTFR(26) HTFR(6)
    x0 += k0; x1 += k1 + 3u;
    HTFR(17) HTFR(29) HTFR(16) HTFR(24)
    x0 += k1; x1 += ks2 + 4u;
    HTFR(13) HTFR(15) HTFR(26) HTFR(6)
    x0 += ks2; x1 += k0 + 5u;
#undef HTFR
    o0 = x0; o1 = x1;
}

// ---------------- launch ----------------
extern "C" void kernel_launch(void* const* d_in, const int* in_sizes, int n_in,
                              void* d_out, int out_size) {
    (void)in_sizes; (void)n_in; (void)out_size;
    const float* x      = (const float*)d_in[0];   // (4,32,32,256)
    const float* theta1 = (const float*)d_in[1];   // (34,32)
    const float* theta2 = (const float*)d_in[2];   // (1058,32)
    const float* Rlf    = (const float*)d_in[3];   // (32,32,2)
    const float* Clf    = (const float*)d_in[4];   // (32,32,2)
    float* out = (float*)d_out;

    Keys kk;
    unsigned ck[8];
    for (int i = 0; i < 4; i++) h_tf2x32(0u, 42u, 0u, (unsigned)i, ck[2 * i], ck[2 * i + 1]);
    kk.v[0] = ck[0]; kk.v[1] = ck[1];   // k1 (pmac1 noise)
    kk.v[2] = ck[6]; kk.v[3] = ck[7];   // k4 (pmac2 noise)
    for (int bank = 0; bank < 2; bank++) {
        unsigned b0 = ck[2 + 2 * bank], b1 = ck[3 + 2 * bank];  // k2 / k3
        for (int j = 0; j < 4; j++)
            h_tf2x32(b0, b1, 0u, (unsigned)j,
                     kk.v[4 + bank * 8 + 2 * j], kk.v[4 + bank * 8 + 2 * j + 1]);
    }

    static int smem_set = 0;
    if (!smem_set) {
        cudaFuncSetAttribute(k_fused, cudaFuncAttributeMaxDynamicSharedMemorySize,
                             SM_TOT * sizeof(float));
        smem_set = 1;
    }

    k_A<<<8448, 256>>>(kk, x, theta1, theta2, Rlf, Clf);
    k_fused<<<128, 1024, SM_TOT * sizeof(float)>>>(kk, out);
}